// round 5
// baseline (speedup 1.0000x reference)
#include <cuda_runtime.h>
#include <math.h>
#include <stdint.h>

#define NDIM     128
#define TABK     512
#define BMAXF    8.0f
#define INV_BMAX 0.125f
#define ATT_SCALE 0.08838834764831845f  // 1/sqrt(128)
#define CAP      1024                    // smem attn cache per graph (nodes)

// -------- persistent device scratch (static allocation only) --------
__device__ float g_M[2][NDIM];               // Wq @ Wk^T
__device__ float g_Kb[2];                    // Wk @ bq
__device__ float g_psi[2][TABK + 1][NDIM];   // charge_embed table psi_j(beta)

__device__ __forceinline__ float silu_f(float z) {
    return z / (1.0f + expf(-z));
}
__device__ __forceinline__ float softplus_fast(float s) {
    return fmaxf(s, 0.0f) + __logf(1.0f + __expf(-fabsf(s)));
}

// ===================== aux kernel: psi table + prep (M, Kb) =====================
// blocks [0, 2*NTB): table; block 2*NTB: prep
#define TPB_T 8
#define NTB   ((TABK + 1 + TPB_T - 1) / TPB_T)   // 65
#define NAUX  (2 * NTB + 1)

__global__ __launch_bounds__(128) void aux_kernel(
    const float* __restrict__ Wq, const float* __restrict__ bq,
    const float* __restrict__ Wk, const float* __restrict__ Wv,
    const float* __restrict__ W1, const float* __restrict__ b1,
    const float* __restrict__ W2, const float* __restrict__ b2) {
    // allow the dependent main kernel to begin launching immediately
    cudaTriggerProgrammaticLaunchCompletion();

    int bid = blockIdx.x;
    int tid = threadIdx.x;

    if (bid < 2 * NTB) {
        // ---- table role: psi_j(beta) for TPB_T beta points ----
        int j  = bid / NTB;
        int tb = bid - j * NTB;
        int n  = tid;
        float u2 = 0.f;                  // U2[j][n] = Wv[j,:] @ W1[:,n]
        #pragma unroll 8
        for (int ee = 0; ee < NDIM; ee++)
            u2 = fmaf(Wv[j * NDIM + ee], W1[ee * NDIM + n], u2);
        __shared__ float h1s[TPB_T][NDIM];
        float b1n = b1[n];
        #pragma unroll
        for (int tt = 0; tt < TPB_T; tt++) {
            int t = tb * TPB_T + tt;
            if (t > TABK) break;
            float x = (float)t / (float)TABK;
            float beta = BMAXF * x * x;
            h1s[tt][n] = silu_f(fmaf(beta, u2, b1n));
        }
        __syncthreads();
        float b2n = b2[n];
        float wv = Wv[j * NDIM + n];
        #pragma unroll
        for (int tt = 0; tt < TPB_T; tt++) {
            int t = tb * TPB_T + tt;
            if (t > TABK) break;
            float y = 0.f;
            #pragma unroll 8
            for (int d = 0; d < NDIM; d++) y = fmaf(h1s[tt][d], W2[d * NDIM + n], y);
            float x = (float)t / (float)TABK;
            float beta = BMAXF * x * x;
            g_psi[j][t][n] = fmaf(beta, wv, silu_f(y + b2n));
        }
    } else {
        // ---- prep role: M, Kb ----
        int e = tid;
        float m0 = 0.f, m1 = 0.f;
        for (int d = 0; d < NDIM; d++) {
            float wq = Wq[e * NDIM + d];
            m0 = fmaf(wq, Wk[d], m0);
            m1 = fmaf(wq, Wk[NDIM + d], m1);
        }
        g_M[0][e] = m0;
        g_M[1][e] = m1;
        if (tid < 2) {
            float kb = 0.f;
            for (int d = 0; d < NDIM; d++) kb = fmaf(Wk[tid * NDIM + d], bq[d], kb);
            g_Kb[tid] = kb;
        }
    }
}

// ========== main: 1 graph per 128-thread block; PDL-dependent on aux =========
#define NW  4
#define NPB (NW * 4)

__global__ __launch_bounds__(128, 10) void main_kernel(
    const float* __restrict__ ns, const float* __restrict__ charge,
    const void* __restrict__ batch_raw, int ngraphs, int nnodes,
    float* __restrict__ out) {
    int tid  = threadIdx.x;
    int g = blockIdx.x;
    if (g >= ngraphs) return;

    __shared__ int   bounds[2];
    __shared__ float warpsum[NW];
    __shared__ float sm_attn[CAP];

    // ---- pre-dependency work: binary search own [n0, n1) from batch ----
    // (batch is a harness input, not produced by aux — legal before the sync)
    if (tid < 2) {
        const int* b32 = (const int*)batch_raw;
        int w = (nnodes >= 8) ? ((nnodes & ~1) - 6) : 0;
        bool is64 = (b32[w + 1] == 0) && (b32[w + 3] == 0) && (b32[w + 5] == 0);
        const long long* b64 = (const long long*)batch_raw;
        long long gv = (long long)(g + tid);
        int lo = 0, hi = nnodes;
        while (lo < hi) {
            int mid = (lo + hi) >> 1;
            long long val = is64 ? b64[mid] : (long long)b32[mid];
            if (val < gv) lo = mid + 1; else hi = mid;
        }
        bounds[tid] = lo;
    }
    float q  = charge[g];
    float r0 = fmaxf(q, 0.f), r1 = fmaxf(-q, 0.f);
    float c0 = fminf(r0, 1.f), c1 = fminf(r1, 1.f);
    int   jj = (q < 0.f) ? 1 : 0;
    float qb = fmaxf(r0, r1);

    // ---- wait for aux grid (HW dependency, no atomics) ----
    cudaGridDependencySynchronize();
    __syncthreads();

    int wid  = tid >> 5, lane = tid & 31;
    int l8   = lane & 7;
    int grp  = lane >> 3;
    int n0 = bounds[0], n1 = bounds[1];
    float cg = c0 * g_Kb[0] + c1 * g_Kb[1];

    // combined projection Mc = c0*M0 + c1*M1, this lane's 16-float slice
    float4 Mc[4];
    #pragma unroll
    for (int jc = 0; jc < 4; jc++) {
        int e = jc * 32 + l8 * 4;
        float4 a = *reinterpret_cast<const float4*>(&g_M[0][e]);
        float4 b = *reinterpret_cast<const float4*>(&g_M[1][e]);
        Mc[jc].x = c0 * a.x + c1 * b.x;
        Mc[jc].y = c0 * a.y + c1 * b.y;
        Mc[jc].z = c0 * a.z + c1 * b.z;
        Mc[jc].w = c0 * a.w + c1 * b.w;
    }

    // ---- phase A: block-local softplus-attention sum ----
    float acc = 0.f;
    for (int base = n0; base < n1; base += NPB) {
        int node = base + wid * 4 + grp;
        bool valid = node < n1;
        float s = 0.f;
        if (valid) {
            const float* row = ns + (long)node * NDIM + l8 * 4;
            #pragma unroll
            for (int jc = 0; jc < 4; jc++) {
                float4 v = *reinterpret_cast<const float4*>(row + jc * 32);
                s += v.x * Mc[jc].x + v.y * Mc[jc].y + v.z * Mc[jc].z + v.w * Mc[jc].w;
            }
        }
        s += __shfl_xor_sync(0xffffffffu, s, 1);
        s += __shfl_xor_sync(0xffffffffu, s, 2);
        s += __shfl_xor_sync(0xffffffffu, s, 4);
        if (valid && l8 == 0) {
            float attn = softplus_fast((s + cg) * ATT_SCALE);
            acc += attn;
            int li = node - n0;
            if (li < CAP) sm_attn[li] = attn;
        }
    }
    #pragma unroll
    for (int o = 16; o > 0; o >>= 1) acc += __shfl_xor_sync(0xffffffffu, acc, o);
    if (lane == 0) warpsum[wid] = acc;
    __syncthreads();
    float asum = warpsum[0] + warpsum[1] + warpsum[2] + warpsum[3];
    float inv = 1.0f / asum;

    // ---- phase B: table epilogue; evict-first reads, streaming stores ----
    for (int base = n0; base < n1; base += NPB) {
        int node = base + wid * 4 + grp;
        if (node >= n1) continue;
        int li = node - n0;
        float attn;
        if (li < CAP) {
            attn = sm_attn[li];
        } else {
            float s = 0.f;
            const float* row = ns + (long)node * NDIM + l8 * 4;
            #pragma unroll
            for (int jc = 0; jc < 4; jc++) {
                float4 v = __ldcs(reinterpret_cast<const float4*>(row + jc * 32));
                s += v.x * Mc[jc].x + v.y * Mc[jc].y + v.z * Mc[jc].z + v.w * Mc[jc].w;
            }
            s += __shfl_xor_sync(0xffffffffu, s, 1);
            s += __shfl_xor_sync(0xffffffffu, s, 2);
            s += __shfl_xor_sync(0xffffffffu, s, 4);
            attn = softplus_fast((s + cg) * ATT_SCALE);
        }
        float beta = attn * inv * qb;
        float tf = (float)TABK * sqrtf(beta * INV_BMAX);
        int idx = (int)tf;
        if (idx > TABK - 1) idx = TABK - 1;
        float f = tf - (float)idx;
        const float* pa = &g_psi[jj][idx][0];
        const float* row = ns + (long)node * NDIM;
        float* orow = out + (long)node * NDIM;
        #pragma unroll
        for (int jc = 0; jc < 4; jc++) {
            int e = jc * 32 + l8 * 4;
            float4 v = __ldcs(reinterpret_cast<const float4*>(row + e));
            float4 a = *reinterpret_cast<const float4*>(pa + e);
            float4 b = *reinterpret_cast<const float4*>(pa + NDIM + e);
            float4 o4;
            o4.x = v.x + fmaf(f, b.x - a.x, a.x);
            o4.y = v.y + fmaf(f, b.y - a.y, a.y);
            o4.z = v.z + fmaf(f, b.z - a.z, a.z);
            o4.w = v.w + fmaf(f, b.w - a.w, a.w);
            __stcs(reinterpret_cast<float4*>(orow + e), o4);
        }
    }
}

extern "C" void kernel_launch(void* const* d_in, const int* in_sizes, int n_in,
                              void* d_out, int out_size) {
    const float* ns     = (const float*)d_in[0];
    const float* charge = (const float*)d_in[1];
    const void*  batch  = (const void*) d_in[2];
    const float* Wq     = (const float*)d_in[3];
    const float* bq     = (const float*)d_in[4];
    const float* Wk     = (const float*)d_in[5];
    const float* Wv     = (const float*)d_in[6];
    const float* W1     = (const float*)d_in[7];
    const float* b1     = (const float*)d_in[8];
    const float* W2     = (const float*)d_in[9];
    const float* b2     = (const float*)d_in[10];
    float* out = (float*)d_out;

    int nnodes  = in_sizes[0] / NDIM;
    int ngraphs = in_sizes[1];

    // primary: aux (table + prep), normal launch on the captured stream
    aux_kernel<<<NAUX, 128>>>(Wq, bq, Wk, Wv, W1, b1, W2, b2);

    // secondary: main, with programmatic dependent launch (overlapped)
    cudaLaunchConfig_t cfg = {};
    cfg.gridDim  = dim3((unsigned)ngraphs, 1, 1);
    cfg.blockDim = dim3(128, 1, 1);
    cfg.dynamicSmemBytes = 0;
    cfg.stream = 0;   // legacy default stream (same one the harness captures)
    cudaLaunchAttribute attrs[1];
    attrs[0].id = cudaLaunchAttributeProgrammaticStreamSerialization;
    attrs[0].val.programmaticStreamSerializationAllowed = 1;
    cfg.attrs = attrs;
    cfg.numAttrs = 1;
    cudaLaunchKernelEx(&cfg, main_kernel, ns, charge, batch, ngraphs, nnodes, out);
}

// round 6
// speedup vs baseline: 1.2670x; 1.2670x over previous
#include <cuda_runtime.h>
#include <math.h>
#include <stdint.h>

#define NDIM     128
#define TABK     512
#define BMAXF    8.0f
#define INV_BMAX 0.125f
#define ATT_SCALE 0.08838834764831845f  // 1/sqrt(128)
#define MAX_GRAPHS 16384
#define CAP      1024                    // smem attn cache per graph (nodes)

// -------- persistent device scratch (static allocation only) --------
__device__ float g_M[2][NDIM];               // Wq @ Wk^T
__device__ float g_Kb[2];                    // Wk @ bq
__device__ int   g_start[MAX_GRAPHS];        // per-graph node offsets
__device__ float g_psi[2][TABK + 1][NDIM];   // charge_embed table psi_j(beta)

__device__ __forceinline__ float silu_f(float z) {
    return z / (1.0f + expf(-z));
}
__device__ __forceinline__ float softplus_fast(float s) {
    return fmaxf(s, 0.0f) + __logf(1.0f + __expf(-fabsf(s)));
}

// ================= aux kernel: table | starts | prep (R3 structure) =========
#define TPB_T 16
#define NTB   ((TABK + 1 + TPB_T - 1) / TPB_T)   // 33
#define SB    40

__global__ __launch_bounds__(256) void aux_kernel(
    const void* __restrict__ batch_raw, int ngraphs, int nnodes,
    const float* __restrict__ Wq, const float* __restrict__ bq,
    const float* __restrict__ Wk, const float* __restrict__ Wv,
    const float* __restrict__ W1, const float* __restrict__ b1,
    const float* __restrict__ W2, const float* __restrict__ b2) {
    int bid = blockIdx.x;
    int tid = threadIdx.x;

    if (bid < 2 * NTB) {
        // ---------------- table role ----------------
        if (tid >= 128) return;
        int j  = bid / NTB;
        int tb = bid - j * NTB;
        int n  = tid;
        float u2 = 0.f;                  // U2[j][n] = Wv[j,:] @ W1[:,n]
        #pragma unroll 8
        for (int ee = 0; ee < NDIM; ee++)
            u2 = fmaf(Wv[j * NDIM + ee], W1[ee * NDIM + n], u2);
        __shared__ float h1s[TPB_T][NDIM];
        float b1n = b1[n];
        #pragma unroll
        for (int tt = 0; tt < TPB_T; tt++) {
            int t = tb * TPB_T + tt;
            if (t > TABK) break;
            float x = (float)t / (float)TABK;
            float beta = BMAXF * x * x;
            h1s[tt][n] = silu_f(fmaf(beta, u2, b1n));
        }
        __syncthreads();
        float b2n = b2[n];
        float wv = Wv[j * NDIM + n];
        for (int tt = 0; tt < TPB_T; tt++) {
            int t = tb * TPB_T + tt;
            if (t > TABK) break;
            float y = 0.f;
            #pragma unroll 8
            for (int d = 0; d < NDIM; d++) y = fmaf(h1s[tt][d], W2[d * NDIM + n], y);
            float x = (float)t / (float)TABK;
            float beta = BMAXF * x * x;
            g_psi[j][t][n] = fmaf(beta, wv, silu_f(y + b2n));
        }
    } else if (bid < 2 * NTB + SB) {
        // ---------------- starts role ----------------
        int g = (bid - 2 * NTB) * 256 + tid;
        if (g > ngraphs) return;
        const int* b32 = (const int*)batch_raw;
        int w = (nnodes >= 8) ? ((nnodes & ~1) - 6) : 0;
        bool is64 = (b32[w + 1] == 0) && (b32[w + 3] == 0) && (b32[w + 5] == 0);
        const long long* b64 = (const long long*)batch_raw;
        long long gv = (long long)g;
        int lo = 0, hi = nnodes;
        while (lo < hi) {
            int mid = (lo + hi) >> 1;
            long long val = is64 ? b64[mid] : (long long)b32[mid];
            if (val < gv) lo = mid + 1; else hi = mid;
        }
        g_start[g] = lo;
    } else {
        // ---------------- prep role (M, Kb) ----------------
        int j = tid >> 7, e = tid & 127;
        const float* wk = Wk + j * NDIM;
        float m = 0.f;
        #pragma unroll 8
        for (int d = 0; d < NDIM; d++) m = fmaf(Wq[e * NDIM + d], wk[d], m);
        g_M[j][e] = m;
        if (tid < 2) {
            float kb = 0.f;
            for (int d = 0; d < NDIM; d++) kb = fmaf(Wk[tid * NDIM + d], bq[d], kb);
            g_Kb[tid] = kb;
        }
    }
}

// ===== main: 1 graph / 128-thread block; 8 nodes per warp-iter in phase A ====
#define NW  4
#define NPB (NW * 8)   // phase A: 8 nodes per warp per iteration
#define NPB_B (NW * 4) // phase B: 4 nodes per warp per iteration

__global__ __launch_bounds__(128, 8) void main_kernel(
    const float* __restrict__ ns, const float* __restrict__ charge,
    float* __restrict__ out, int ngraphs) {
    // HW dependency wait on aux grid (PDL); before ANY global access
    cudaGridDependencySynchronize();

    int tid  = threadIdx.x;
    int wid  = tid >> 5, lane = tid & 31;
    int l8   = lane & 7;
    int grp  = lane >> 3;
    __shared__ float warpsum[NW];
    __shared__ float sm_attn[CAP];

    int g = blockIdx.x;
    if (g >= ngraphs) return;

    float q  = charge[g];
    float r0 = fmaxf(q, 0.f), r1 = fmaxf(-q, 0.f);
    float c0 = fminf(r0, 1.f), c1 = fminf(r1, 1.f);
    float cg = c0 * g_Kb[0] + c1 * g_Kb[1];
    int   jj = (q < 0.f) ? 1 : 0;
    float qb = fmaxf(r0, r1);
    int n0 = g_start[g], n1 = g_start[g + 1];

    // combined projection Mc = c0*M0 + c1*M1, this lane's 16-float slice
    float4 Mc[4];
    #pragma unroll
    for (int jc = 0; jc < 4; jc++) {
        int e = jc * 32 + l8 * 4;
        float4 a = *reinterpret_cast<const float4*>(&g_M[0][e]);
        float4 b = *reinterpret_cast<const float4*>(&g_M[1][e]);
        Mc[jc].x = c0 * a.x + c1 * b.x;
        Mc[jc].y = c0 * a.y + c1 * b.y;
        Mc[jc].z = c0 * a.z + c1 * b.z;
        Mc[jc].w = c0 * a.w + c1 * b.w;
    }

    // ---- phase A: 2 nodes per 8-lane group per iter; all loads front-batched --
    float acc = 0.f;
    for (int base = n0; base < n1; base += NPB) {
        int nd0 = base + wid * 8 + grp * 2;
        int nd1 = nd0 + 1;
        bool v0 = nd0 < n1, v1 = nd1 < n1;
        float4 va[4], vb[4];
        const float* ra = ns + (long)nd0 * NDIM + l8 * 4;
        const float* rb = ns + (long)nd1 * NDIM + l8 * 4;
        #pragma unroll
        for (int jc = 0; jc < 4; jc++)
            va[jc] = v0 ? *reinterpret_cast<const float4*>(ra + jc * 32)
                        : make_float4(0.f, 0.f, 0.f, 0.f);
        #pragma unroll
        for (int jc = 0; jc < 4; jc++)
            vb[jc] = v1 ? *reinterpret_cast<const float4*>(rb + jc * 32)
                        : make_float4(0.f, 0.f, 0.f, 0.f);
        float s0 = 0.f, s1 = 0.f;
        #pragma unroll
        for (int jc = 0; jc < 4; jc++) {
            s0 += va[jc].x * Mc[jc].x + va[jc].y * Mc[jc].y
                + va[jc].z * Mc[jc].z + va[jc].w * Mc[jc].w;
            s1 += vb[jc].x * Mc[jc].x + vb[jc].y * Mc[jc].y
                + vb[jc].z * Mc[jc].z + vb[jc].w * Mc[jc].w;
        }
        s0 += __shfl_xor_sync(0xffffffffu, s0, 1);
        s1 += __shfl_xor_sync(0xffffffffu, s1, 1);
        s0 += __shfl_xor_sync(0xffffffffu, s0, 2);
        s1 += __shfl_xor_sync(0xffffffffu, s1, 2);
        s0 += __shfl_xor_sync(0xffffffffu, s0, 4);
        s1 += __shfl_xor_sync(0xffffffffu, s1, 4);
        if (l8 == 0) {
            if (v0) {
                float a0 = softplus_fast((s0 + cg) * ATT_SCALE);
                acc += a0;
                int li = nd0 - n0;
                if (li < CAP) sm_attn[li] = a0;
            }
            if (v1) {
                float a1 = softplus_fast((s1 + cg) * ATT_SCALE);
                acc += a1;
                int li = nd1 - n0;
                if (li < CAP) sm_attn[li] = a1;
            }
        }
    }
    #pragma unroll
    for (int o = 16; o > 0; o >>= 1) acc += __shfl_xor_sync(0xffffffffu, acc, o);
    if (lane == 0) warpsum[wid] = acc;
    __syncthreads();
    float asum = warpsum[0] + warpsum[1] + warpsum[2] + warpsum[3];
    float inv = 1.0f / asum;

    // ---- phase B: table epilogue; evict-first reads, streaming stores ----
    for (int base = n0; base < n1; base += NPB_B) {
        int node = base + wid * 4 + grp;
        if (node >= n1) continue;
        int li = node - n0;
        float attn;
        if (li < CAP) {
            attn = sm_attn[li];
        } else {
            float s = 0.f;
            const float* row = ns + (long)node * NDIM + l8 * 4;
            #pragma unroll
            for (int jc = 0; jc < 4; jc++) {
                float4 v = __ldcs(reinterpret_cast<const float4*>(row + jc * 32));
                s += v.x * Mc[jc].x + v.y * Mc[jc].y + v.z * Mc[jc].z + v.w * Mc[jc].w;
            }
            s += __shfl_xor_sync(0xffffffffu, s, 1);
            s += __shfl_xor_sync(0xffffffffu, s, 2);
            s += __shfl_xor_sync(0xffffffffu, s, 4);
            attn = softplus_fast((s + cg) * ATT_SCALE);
        }
        float beta = attn * inv * qb;
        float tf = (float)TABK * sqrtf(beta * INV_BMAX);
        int idx = (int)tf;
        if (idx > TABK - 1) idx = TABK - 1;
        float f = tf - (float)idx;
        const float* pa = &g_psi[jj][idx][0];
        const float* row = ns + (long)node * NDIM;
        float* orow = out + (long)node * NDIM;
        #pragma unroll
        for (int jc = 0; jc < 4; jc++) {
            int e = jc * 32 + l8 * 4;
            float4 v = __ldcs(reinterpret_cast<const float4*>(row + e));
            float4 a = *reinterpret_cast<const float4*>(pa + e);
            float4 b = *reinterpret_cast<const float4*>(pa + NDIM + e);
            float4 o4;
            o4.x = v.x + fmaf(f, b.x - a.x, a.x);
            o4.y = v.y + fmaf(f, b.y - a.y, a.y);
            o4.z = v.z + fmaf(f, b.z - a.z, a.z);
            o4.w = v.w + fmaf(f, b.w - a.w, a.w);
            __stcs(reinterpret_cast<float4*>(orow + e), o4);
        }
    }
}

extern "C" void kernel_launch(void* const* d_in, const int* in_sizes, int n_in,
                              void* d_out, int out_size) {
    const float* ns     = (const float*)d_in[0];
    const float* charge = (const float*)d_in[1];
    const void*  batch  = (const void*) d_in[2];
    const float* Wq     = (const float*)d_in[3];
    const float* bq     = (const float*)d_in[4];
    const float* Wk     = (const float*)d_in[5];
    const float* Wv     = (const float*)d_in[6];
    const float* W1     = (const float*)d_in[7];
    const float* b1     = (const float*)d_in[8];
    const float* W2     = (const float*)d_in[9];
    const float* b2     = (const float*)d_in[10];
    float* out = (float*)d_out;

    int nnodes  = in_sizes[0] / NDIM;
    int ngraphs = in_sizes[1];

    aux_kernel<<<2 * NTB + SB + 1, 256>>>(batch, ngraphs, nnodes,
                                          Wq, bq, Wk, Wv, W1, b1, W2, b2);

    // PDL: implicit end-of-aux trigger; main blocks prestage during aux
    cudaLaunchConfig_t cfg = {};
    cfg.gridDim  = dim3((unsigned)ngraphs, 1, 1);
    cfg.blockDim = dim3(128, 1, 1);
    cfg.dynamicSmemBytes = 0;
    cfg.stream = 0;
    cudaLaunchAttribute attrs[1];
    attrs[0].id = cudaLaunchAttributeProgrammaticStreamSerialization;
    attrs[0].val.programmaticStreamSerializationAllowed = 1;
    cfg.attrs = attrs;
    cfg.numAttrs = 1;
    cudaLaunchKernelEx(&cfg, main_kernel, ns, charge, out, ngraphs);
}